// round 8
// baseline (speedup 1.0000x reference)
#include <cuda_runtime.h>
#include <cstdint>
#include <math.h>

#define B_    64
#define NREF  256
#define NPTS  2048
#define DIM   128
#define LOG_WX (-5.5451748845f)   /* log(1/256 + 1e-8)  */
#define LOG_WY (-7.6245985065f)   /* log(1/2048 + 1e-8) */
#define ITERS 100
#define FULLM 0xffffffffu
#define NEG_INF __int_as_float(0xff800000)
#define TOLS  0.02f

#define STEP   0.00390625f        /* 2^-8, exact */
#define QSCALE 256000.0f          /* 1000 * 256  */
#define QMAXF  8388607.0f         /* 2^23 - 1    */
#define MAGIC  0x4B000000u        /* 2^23 float  */
#define BIASV  32768.0f           /* STEP * 2^23 */
#define MARG   25.0f

// -------- device scratch (allocation-free per harness rules) --------
__device__ __align__(16) unsigned short g_Clo [(size_t)B_*NREF*NPTS]; // natural order
__device__ __align__(16) unsigned char  g_Chi [(size_t)B_*NREF*NPTS];
__device__ __align__(16) unsigned short g_CloP[(size_t)B_*NREF*NPTS]; // column-permuted
__device__ __align__(16) unsigned char  g_ChiP[(size_t)B_*NREF*NPTS];
__device__ unsigned char  g_amin[B_*NPTS];       // per natural col: argmin row
__device__ unsigned short g_perm[B_*NPTS];       // slot k -> natural col
__device__ float g_cminN[(size_t)B_*8*NPTS];     // natural col 32-row-chunk mins (scaled)
__device__ float g_cminP[(size_t)B_*8*NPTS];     // permuted
__device__ float g_rmin [(size_t)B_*NREF*32];    // per-row 64-col-chunk mins, permuted (scaled)
__device__ float g_us[B_*NREF];
__device__ float g_vs[B_*NPTS];                  // permuted order
__device__ float g_x2[B_*NPTS];
__device__ float g_r2[NREF];

__device__ __forceinline__ unsigned int smem_u32(const void* p) {
    unsigned int a;
    asm("{ .reg .u64 t; cvta.to.shared.u64 t, %1; cvt.u32.u64 %0, t; }" : "=r"(a) : "l"(p));
    return a;
}
__device__ __forceinline__ void st_peer_f32(unsigned int local_addr, int peer, float v) {
    unsigned int rem;
    asm volatile("mapa.shared::cluster.u32 %0, %1, %2;" : "=r"(rem) : "r"(local_addr), "r"(peer));
    asm volatile("st.shared::cluster.f32 [%0], %1;" :: "r"(rem), "f"(v) : "memory");
}
__device__ __forceinline__ void cluster_sync_() {
    asm volatile("barrier.cluster.arrive.aligned;" ::: "memory");
    asm volatile("barrier.cluster.wait.aligned;" ::: "memory");
}

// -------- squared norms --------
__global__ void aux_kernel(const float* __restrict__ X, const float* __restrict__ REF) {
    int gw   = (blockIdx.x * blockDim.x + threadIdx.x) >> 5;
    int lane = threadIdx.x & 31;
    if (gw < B_ * NPTS) {
        const float* r = X + (size_t)gw * DIM;
        float s = 0.f;
        #pragma unroll
        for (int k = lane; k < DIM; k += 32) { float t = r[k]; s = fmaf(t, t, s); }
        #pragma unroll
        for (int o = 16; o; o >>= 1) s += __shfl_xor_sync(FULLM, s, o);
        if (!lane) g_x2[gw] = s;
    } else if (gw < B_ * NPTS + NREF) {
        int i = gw - B_ * NPTS;
        const float* r = REF + i * DIM;
        float s = 0.f;
        #pragma unroll
        for (int k = lane; k < DIM; k += 32) { float t = r[k]; s = fmaf(t, t, s); }
        #pragma unroll
        for (int o = 16; o; o >>= 1) s += __shfl_xor_sync(FULLM, s, o);
        if (!lane) g_r2[i] = s;
    }
}

// -------- build 24-bit quantized cost (natural order) --------
__global__ __launch_bounds__(256) void c_kernel(const float* __restrict__ X,
                                                const float* __restrict__ REF) {
    __shared__ float sA[32][65];
    __shared__ float sB[32][65];
    int b  = blockIdx.z;
    int i0 = blockIdx.y * 64, j0 = blockIdx.x * 64;
    int tid = threadIdx.x;
    int ti = tid >> 4, tj = tid & 15;
    const float* Xb = X + (size_t)b * NPTS * DIM;

    float acc[4][4];
    #pragma unroll
    for (int a = 0; a < 4; a++)
        #pragma unroll
        for (int c = 0; c < 4; c++) acc[a][c] = 0.f;

    for (int k0 = 0; k0 < DIM; k0 += 32) {
        #pragma unroll
        for (int r = 0; r < 8; r++) {
            int e  = r * 256 + tid;
            int ii = e >> 5, kk = e & 31;
            sA[kk][ii] = REF[(i0 + ii) * DIM + k0 + kk];
            sB[kk][ii] = Xb[(size_t)(j0 + ii) * DIM + k0 + kk];
        }
        __syncthreads();
        #pragma unroll
        for (int kk = 0; kk < 32; kk++) {
            float a0 = sA[kk][ti*4+0], a1 = sA[kk][ti*4+1], a2 = sA[kk][ti*4+2], a3 = sA[kk][ti*4+3];
            float b0 = sB[kk][tj*4+0], b1 = sB[kk][tj*4+1], b2 = sB[kk][tj*4+2], b3 = sB[kk][tj*4+3];
            acc[0][0]=fmaf(a0,b0,acc[0][0]); acc[0][1]=fmaf(a0,b1,acc[0][1]); acc[0][2]=fmaf(a0,b2,acc[0][2]); acc[0][3]=fmaf(a0,b3,acc[0][3]);
            acc[1][0]=fmaf(a1,b0,acc[1][0]); acc[1][1]=fmaf(a1,b1,acc[1][1]); acc[1][2]=fmaf(a1,b2,acc[1][2]); acc[1][3]=fmaf(a1,b3,acc[1][3]);
            acc[2][0]=fmaf(a2,b0,acc[2][0]); acc[2][1]=fmaf(a2,b1,acc[2][1]); acc[2][2]=fmaf(a2,b2,acc[2][2]); acc[2][3]=fmaf(a2,b3,acc[2][3]);
            acc[3][0]=fmaf(a3,b0,acc[3][0]); acc[3][1]=fmaf(a3,b1,acc[3][1]); acc[3][2]=fmaf(a3,b2,acc[3][2]); acc[3][3]=fmaf(a3,b3,acc[3][3]);
        }
        __syncthreads();
    }

    float x20 = g_x2[b*NPTS + j0 + tj*4 + 0];
    float x21 = g_x2[b*NPTS + j0 + tj*4 + 1];
    float x22 = g_x2[b*NPTS + j0 + tj*4 + 2];
    float x23 = g_x2[b*NPTS + j0 + tj*4 + 3];
    #pragma unroll
    for (int a = 0; a < 4; a++) {
        int i = i0 + ti*4 + a;
        float r2 = g_r2[i];
        float d0 = sqrtf(fmaxf(r2 + x20 - 2.f*acc[a][0], 0.f));
        float d1 = sqrtf(fmaxf(r2 + x21 - 2.f*acc[a][1], 0.f));
        float d2 = sqrtf(fmaxf(r2 + x22 - 2.f*acc[a][2], 0.f));
        float d3 = sqrtf(fmaxf(r2 + x23 - 2.f*acc[a][3], 0.f));
        unsigned q0 = __float2uint_rn(fminf(QSCALE*d0, QMAXF));
        unsigned q1 = __float2uint_rn(fminf(QSCALE*d1, QMAXF));
        unsigned q2 = __float2uint_rn(fminf(QSCALE*d2, QMAXF));
        unsigned q3 = __float2uint_rn(fminf(QSCALE*d3, QMAXF));
        size_t idx = ((size_t)b*NREF + i)*NPTS + j0 + tj*4;
        ushort4 lo;
        lo.x = (unsigned short)(q0 & 0xFFFF);
        lo.y = (unsigned short)(q1 & 0xFFFF);
        lo.z = (unsigned short)(q2 & 0xFFFF);
        lo.w = (unsigned short)(q3 & 0xFFFF);
        *(ushort4*)(&g_Clo[idx]) = lo;
        uchar4 hi;
        hi.x = (unsigned char)(q0 >> 16);
        hi.y = (unsigned char)(q1 >> 16);
        hi.z = (unsigned char)(q2 >> 16);
        hi.w = (unsigned char)(q3 >> 16);
        *(uchar4*)(&g_Chi[idx]) = hi;
    }
}

// -------- per-column argmin row + 32-row-chunk mins (natural order) --------
__global__ __launch_bounds__(256) void colmin_kernel() {
    int g = blockIdx.x * 256 + threadIdx.x;
    int b = g >> 11, j = g & (NPTS - 1);
    const unsigned short* lo = g_Clo + (size_t)b*NREF*NPTS + j;
    const unsigned char*  hi = g_Chi + (size_t)b*NREF*NPTS + j;
    unsigned best = 0xFFFFFFFFu; int barg = 0;
    for (int ch = 0; ch < 8; ch++) {
        unsigned cmin = 0xFFFFFFFFu;
        #pragma unroll 8
        for (int r = 0; r < 32; r++) {
            int i = ch*32 + r;
            unsigned q = lo[(size_t)i*NPTS] | ((unsigned)hi[(size_t)i*NPTS] << 16);
            cmin = min(cmin, q);
            if (q < best) { best = q; barg = i; }
        }
        g_cminN[((size_t)b*8 + ch)*NPTS + j] = STEP * (float)cmin;
    }
    g_amin[g] = (unsigned char)barg;
}

// -------- deterministic counting sort of columns by argmin row (per batch) --------
__global__ __launch_bounds__(256) void sort_kernel() {
    __shared__ unsigned char  sa[NPTS];
    __shared__ unsigned short sp[NPTS];
    __shared__ int offs[NREF];
    int b = blockIdx.x, tid = threadIdx.x;
    for (int k = tid; k < NPTS; k += 256) sa[k] = g_amin[b*NPTS + k];
    __syncthreads();
    if (tid == 0) {
        for (int i = 0; i < NREF; i++) offs[i] = 0;
        for (int k = 0; k < NPTS; k++) offs[sa[k]]++;
        int acc = 0;
        for (int i = 0; i < NREF; i++) { int h = offs[i]; offs[i] = acc; acc += h; }
        for (int k = 0; k < NPTS; k++) { int a = sa[k]; sp[offs[a]++] = (unsigned short)k; }
    }
    __syncthreads();
    for (int k = tid; k < NPTS; k += 256) {
        int src = sp[k];
        g_perm[b*NPTS + k] = (unsigned short)src;
        #pragma unroll
        for (int ch = 0; ch < 8; ch++)
            g_cminP[((size_t)b*8 + ch)*NPTS + k] = g_cminN[((size_t)b*8 + ch)*NPTS + src];
    }
}

// -------- permute columns (SMEM staged) + per-row 64-col-chunk mins --------
__global__ __launch_bounds__(128) void permute_kernel() {
    __shared__ unsigned short sperm[NPTS];       // 4KB
    __shared__ unsigned short slo[4][NPTS];      // 16KB
    __shared__ unsigned char  shi[4][NPTS];      // 8KB
    int row0 = blockIdx.x * 4;                   // global row index (b*NREF + i)
    int b = row0 >> 8;
    int tid = threadIdx.x, lane = tid & 31, w = tid >> 5;

    for (int k = tid; k < NPTS; k += 128) sperm[k] = g_perm[b*NPTS + k];
    {
        const unsigned* plo = (const unsigned*)(g_Clo + (size_t)(row0 + w)*NPTS);
        unsigned* dlo = (unsigned*)slo[w];
        for (int k = lane; k < NPTS/2; k += 32) dlo[k] = plo[k];
        const unsigned* phi = (const unsigned*)(g_Chi + (size_t)(row0 + w)*NPTS);
        unsigned* dhi = (unsigned*)shi[w];
        for (int k = lane; k < NPTS/4; k += 32) dhi[k] = phi[k];
    }
    __syncthreads();

    unsigned short* outLo = g_CloP + (size_t)(row0 + w)*NPTS;
    unsigned char*  outHi = g_ChiP + (size_t)(row0 + w)*NPTS;
    for (int c = 0; c < 32; c++) {
        int k0 = c*64 + 2*lane;
        int s0 = sperm[k0], s1 = sperm[k0 + 1];
        unsigned l0 = slo[w][s0], l1 = slo[w][s1];
        unsigned h0 = shi[w][s0], h1 = shi[w][s1];
        unsigned q0 = l0 | (h0 << 16), q1 = l1 | (h1 << 16);
        ((unsigned*)outLo)[c*32 + lane] = l0 | (l1 << 16);
        ((unsigned short*)outHi)[c*32 + lane] = (unsigned short)(h0 | (h1 << 8));
        unsigned qm = min(q0, q1);
        #pragma unroll
        for (int o = 16; o; o >>= 1) qm = min(qm, __shfl_xor_sync(FULLM, qm, o));
        if (lane == 0) g_rmin[(size_t)(row0 + w)*32 + c] = STEP * (float)qm;
    }
}

// -------- v-phase chunk evaluator (32 rows x 2 cols, online LSE) --------
__device__ __forceinline__ void v_eval_chunk(
    const unsigned short* CbLo, const unsigned char* CbHi,
    const float* usb, int ibase, int c, int tid,
    float& m0, float& s0, float& m1, float& s1)
{
    #pragma unroll 1
    for (int ii = 0; ii < 32; ii += 4) {
        unsigned lo32[4]; unsigned hi16[4];
        #pragma unroll
        for (int k = 0; k < 4; k++) {
            int i = ibase + c*32 + ii + k;
            lo32[k] = ((const unsigned*)(CbLo + (size_t)i*NPTS))[tid];
            hi16[k] = ((const unsigned short*)(CbHi + (size_t)i*NPTS))[tid];
        }
        #pragma unroll
        for (int k = 0; k < 4; k++) {
            int i = ibase + c*32 + ii + k;
            float ub = usb[i];
            float f0 = __uint_as_float(MAGIC | ((hi16[k] << 16) & 0xFF0000u) | (lo32[k] & 0xFFFFu));
            float f1 = __uint_as_float(MAGIC | ((hi16[k] <<  8) & 0xFF0000u) | (lo32[k] >> 16));
            float z0 = fmaf(-STEP, f0, ub);
            float z1 = fmaf(-STEP, f1, ub);
            if (z0 > m0 - MARG) { float nm = fmaxf(m0, z0); s0 = s0*__expf(m0-nm) + __expf(z0-nm); m0 = nm; }
            if (z1 > m1 - MARG) { float nm = fmaxf(m1, z1); s1 = s1*__expf(m1-nm) + __expf(z1-nm); m1 = nm; }
        }
    }
}

// -------- cluster Sinkhorn with exact chunk screening --------
__global__ __launch_bounds__(1024, 1) __cluster_dims__(2, 1, 1)
void sinkhorn_cluster() {
    __shared__ __align__(16) float us [NREF];
    __shared__ __align__(16) float usb[NREF];
    __shared__ __align__(16) float vs [NPTS];
    __shared__ __align__(16) float vsb[NPTS];
    __shared__ __align__(16) float pmP[NPTS];
    __shared__ __align__(16) float psP[NPTS];
    __shared__ float maxvs[32];
    __shared__ float maxus[4];
    __shared__ float red[32];
    __shared__ float s_dmu, s_dmuP;
    __shared__ int   s_done;

    int b = blockIdx.x >> 1, rank = blockIdx.x & 1, peer = rank ^ 1;
    int tid = threadIdx.x, lane = tid & 31, w = tid >> 5;
    const unsigned short* CbLo = g_CloP + (size_t)b*NREF*NPTS;
    const unsigned char*  CbHi = g_ChiP + (size_t)b*NREF*NPTS;

    unsigned pm_a = smem_u32(pmP), ps_a = smem_u32(psP), dmu_a = smem_u32(&s_dmuP);

    // constant preloads
    float rq[4];
    #pragma unroll
    for (int r = 0; r < 4; r++)
        rq[r] = g_rmin[(size_t)(b*NREF + rank*128 + w*4 + r)*32 + lane];
    float cq0[4], cq1[4];
    #pragma unroll
    for (int c = 0; c < 4; c++) {
        cq0[c] = g_cminP[((size_t)b*8 + rank*4 + c)*NPTS + 2*tid];
        cq1[c] = g_cminP[((size_t)b*8 + rank*4 + c)*NPTS + 2*tid + 1];
    }

    if (tid < NREF) { us[tid] = 0.f; usb[tid] = BIASV; }
    vs[tid] = 0.f;  vs[tid + 1024] = 0.f;
    vsb[tid] = BIASV; vsb[tid + 1024] = BIASV;
    if (w == 0) maxvs[lane] = 0.f;
    __syncthreads();

    for (int iter = 0; iter < ITERS; iter++) {
        // ======== u phase: warp w -> rows rank*128 + w*4..+3, screened ========
        float udmax = 0.f;
        #pragma unroll 1
        for (int r = 0; r < 4; r++) {
            int i = rank*128 + w*4 + r;
            const unsigned*       rowLo = (const unsigned*)(CbLo + (size_t)i*NPTS);
            const unsigned short* rowHi = (const unsigned short*)(CbHi + (size_t)i*NPTS);
            float bound = maxvs[lane] - rq[r];
            float mb = bound;
            #pragma unroll
            for (int o = 16; o; o >>= 1) mb = fmaxf(mb, __shfl_xor_sync(FULLM, mb, o));
            unsigned bbm = __ballot_sync(FULLM, bound == mb);
            int cstar = __ffs(bbm) - 1;
            float m, s;
            {   // exact eval of best-bound chunk -> m_lb
                unsigned lo = rowLo[cstar*32 + lane];
                unsigned hi = rowHi[cstar*32 + lane];
                float f0 = __uint_as_float(MAGIC | ((hi << 16) & 0xFF0000u) | (lo & 0xFFFFu));
                float f1 = __uint_as_float(MAGIC | ((hi <<  8) & 0xFF0000u) | (lo >> 16));
                float2 vv = *(const float2*)&vsb[cstar*64 + 2*lane];
                float z0 = fmaf(-STEP, f0, vv.x);
                float z1 = fmaf(-STEP, f1, vv.y);
                m = fmaxf(z0, z1);
                s = 0.f;
                if (z0 > m - MARG) s += __expf(z0 - m);
                if (z1 > m - MARG) s += __expf(z1 - m);
            }
            float mlb = m;
            #pragma unroll
            for (int o = 16; o; o >>= 1) mlb = fmaxf(mlb, __shfl_xor_sync(FULLM, mlb, o));
            unsigned act = __ballot_sync(FULLM, bound > mlb - MARG) & ~(1u << cstar);
            while (act) {
                int c = __ffs(act) - 1; act &= act - 1;
                unsigned lo = rowLo[c*32 + lane];
                unsigned hi = rowHi[c*32 + lane];
                float f0 = __uint_as_float(MAGIC | ((hi << 16) & 0xFF0000u) | (lo & 0xFFFFu));
                float f1 = __uint_as_float(MAGIC | ((hi <<  8) & 0xFF0000u) | (lo >> 16));
                float2 vv = *(const float2*)&vsb[c*64 + 2*lane];
                float z0 = fmaf(-STEP, f0, vv.x);
                float z1 = fmaf(-STEP, f1, vv.y);
                float lm = fmaxf(z0, z1);
                if (lm > m - MARG) {
                    float nm = fmaxf(m, lm);
                    s *= __expf(m - nm);
                    if (z0 > nm - MARG) s += __expf(z0 - nm);
                    if (z1 > nm - MARG) s += __expf(z1 - nm);
                    m = nm;
                }
            }
            #pragma unroll
            for (int o = 16; o; o >>= 1) {
                float mo = __shfl_xor_sync(FULLM, m, o);
                float so = __shfl_xor_sync(FULLM, s, o);
                float nm = fmaxf(m, mo);
                s = s*__expf(m - nm) + so*__expf(mo - nm);
                m = nm;
            }
            float nu = LOG_WX - (m + __logf(s));
            if (lane == 0) {
                udmax = fmaxf(udmax, fabsf(nu - us[i]));
                us[i] = nu; usb[i] = nu + BIASV;
            }
        }
        if (lane == 0) red[w] = udmax;
        __syncthreads();
        if (w < 4) {   // maxus over own 4 row-chunks
            float mu = us[rank*128 + w*32 + lane];
            #pragma unroll
            for (int o = 16; o; o >>= 1) mu = fmaxf(mu, __shfl_xor_sync(FULLM, mu, o));
            if (lane == 0) maxus[w] = mu;
        }
        if (tid == 0) {
            float dm = 0.f;
            #pragma unroll
            for (int q = 0; q < 32; q++) dm = fmaxf(dm, red[q]);
            s_dmu = dm;
        }
        __syncthreads();

        // ======== v partials over own rows: thread -> cols 2tid, 2tid+1, screened ========
        int j0 = 2*tid;
        int ibase = rank*128;
        float m0 = NEG_INF, s0 = 0.f, m1 = NEG_INF, s1 = 0.f;
        {
            float bc[4];
            #pragma unroll
            for (int c = 0; c < 4; c++)
                bc[c] = maxus[c] - fminf(cq0[c], cq1[c]);
            int cb = 0; float bbv = bc[0];
            if (bc[1] > bbv) { bbv = bc[1]; cb = 1; }
            if (bc[2] > bbv) { bbv = bc[2]; cb = 2; }
            if (bc[3] > bbv) { bbv = bc[3]; cb = 3; }
            v_eval_chunk(CbLo, CbHi, usb, ibase, cb, tid, m0, s0, m1, s1);
            #pragma unroll
            for (int c = 0; c < 4; c++) {
                if (c == cb) continue;
                bool need = ((maxus[c] - cq0[c]) > m0 - MARG) | ((maxus[c] - cq1[c]) > m1 - MARG);
                if (need) v_eval_chunk(CbLo, CbHi, usb, ibase, c, tid, m0, s0, m1, s1);
            }
        }
        st_peer_f32(pm_a + 4u*j0,     peer, m0);
        st_peer_f32(ps_a + 4u*j0,     peer, s0);
        st_peer_f32(pm_a + 4u*(j0+1), peer, m1);
        st_peer_f32(ps_a + 4u*(j0+1), peer, s1);
        if (tid == 0) st_peer_f32(dmu_a, peer, s_dmu);

        cluster_sync_();          // publish partials both ways

        // ======== merge partials -> full v + chunk maxes ========
        float vdm;
        {
            float pm = pmP[j0], ps = psP[j0];
            float M  = fmaxf(m0, pm);
            float S  = s0*__expf(m0 - M) + ps*__expf(pm - M);
            float nv0 = LOG_WY - (M + __logf(S));
            float pm2 = pmP[j0+1], ps2 = psP[j0+1];
            float M2  = fmaxf(m1, pm2);
            float S2  = s1*__expf(m1 - M2) + ps2*__expf(pm2 - M2);
            float nv1 = LOG_WY - (M2 + __logf(S2));
            vdm = fmaxf(fabsf(nv0 - vs[j0]), fabsf(nv1 - vs[j0+1]));
            vs[j0]   = nv0;  vsb[j0]   = nv0 + BIASV;
            vs[j0+1] = nv1;  vsb[j0+1] = nv1 + BIASV;
            float cm = fmaxf(nv0, nv1);     // warp w covers cols 64w..64w+63 = chunk w
            #pragma unroll
            for (int o = 16; o; o >>= 1) cm = fmaxf(cm, __shfl_xor_sync(FULLM, cm, o));
            if (lane == 0) maxvs[w] = cm;
        }

        // ======== convergence ========
        #pragma unroll
        for (int o = 16; o; o >>= 1) vdm = fmaxf(vdm, __shfl_xor_sync(FULLM, vdm, o));
        if (lane == 0) red[w] = vdm;
        __syncthreads();
        if (tid == 0) {
            float dm = 0.f;
            #pragma unroll
            for (int q = 0; q < 32; q++) dm = fmaxf(dm, red[q]);
            dm = fmaxf(dm, fmaxf(s_dmu, s_dmuP));
            s_done = (dm < TOLS) ? 1 : 0;
        }
        cluster_sync_();          // merge done -> partial bufs reusable; s_done visible
        if (s_done) break;
    }

    if (tid < 128) g_us[b*NREF + rank*128 + tid] = us[rank*128 + tid];
    if (rank == 0) {
        g_vs[b*NPTS + tid]        = vs[tid];
        g_vs[b*NPTS + tid + 1024] = vs[tid + 1024];
    }
    cluster_sync_();
}

// -------- barycenters: chunk screen + ballot X gather (via perm) --------
__global__ __launch_bounds__(256) void bary_kernel(const float* __restrict__ X,
                                                   const float* __restrict__ REF,
                                                   float* __restrict__ out) {
    __shared__ float vsb[NPTS];
    __shared__ float maxvs[32];
    int b = blockIdx.y, tid = threadIdx.x, lane = tid & 31, w = tid >> 5;
    const float* vrow = g_vs + b * NPTS;
    #pragma unroll
    for (int r = 0; r < NPTS/256; r++) vsb[r*256 + tid] = vrow[r*256 + tid] + BIASV;
    __syncthreads();
    if (tid < 32) {
        float mv = NEG_INF;
        for (int q = 0; q < 64; q++) mv = fmaxf(mv, vsb[tid*64 + q]);
        maxvs[tid] = mv - BIASV;
    }
    __syncthreads();

    int i = blockIdx.x * 8 + w;
    float ui = g_us[b*NREF + i];
    const unsigned*       rowLo = (const unsigned*)(g_CloP + ((size_t)b*NREF + i)*NPTS);
    const unsigned short* rowHi = (const unsigned short*)(g_ChiP + ((size_t)b*NREF + i)*NPTS);
    const unsigned short* prm = g_perm + b*NPTS;
    const float* Xb = X + (size_t)b * NPTS * DIM;

    float rqv = g_rmin[(size_t)(b*NREF + i)*32 + lane];
    float bound = ui + maxvs[lane] - rqv;
    unsigned act = __ballot_sync(FULLM, bound > -41.f);

    float acc0 = 0.f, acc1 = 0.f, acc2 = 0.f, acc3 = 0.f, den = 0.f;
    while (act) {
        int c = __ffs(act) - 1; act &= act - 1;
        unsigned lo = rowLo[c*32 + lane];
        unsigned hi = rowHi[c*32 + lane];
        float f0 = __uint_as_float(MAGIC | ((hi << 16) & 0xFF0000u) | (lo & 0xFFFFu));
        float f1 = __uint_as_float(MAGIC | ((hi <<  8) & 0xFF0000u) | (lo >> 16));
        float2 vv = *(const float2*)&vsb[c*64 + 2*lane];
        float z0 = ui + fmaf(-STEP, f0, vv.x);
        float z1 = ui + fmaf(-STEP, f1, vv.y);
        float w0 = (z0 > -40.f) ? __expf(z0) : 0.f;
        float w1 = (z1 > -40.f) ? __expf(z1) : 0.f;
        unsigned live = __ballot_sync(FULLM, (w0 > 0.f) | (w1 > 0.f));
        while (live) {
            int p = __ffs(live) - 1; live &= live - 1;
            float a0 = __shfl_sync(FULLM, w0, p);
            float a1 = __shfl_sync(FULLM, w1, p);
            int kk = c*64 + 2*p;
            if (a0 > 0.f) {
                const float* xr = Xb + (size_t)prm[kk] * DIM;
                acc0 = fmaf(a0, xr[lane], acc0);   acc1 = fmaf(a0, xr[lane+32], acc1);
                acc2 = fmaf(a0, xr[lane+64], acc2); acc3 = fmaf(a0, xr[lane+96], acc3);
                den += a0;
            }
            if (a1 > 0.f) {
                const float* xr = Xb + (size_t)prm[kk+1] * DIM;
                acc0 = fmaf(a1, xr[lane], acc0);   acc1 = fmaf(a1, xr[lane+32], acc1);
                acc2 = fmaf(a1, xr[lane+64], acc2); acc3 = fmaf(a1, xr[lane+96], acc3);
                den += a1;
            }
        }
    }
    float inv = 1.f / (den + 1e-8f);
    float* orow = out + ((size_t)b*NREF + i) * DIM;
    orow[lane     ] = acc0 * inv - REF[i*DIM + lane     ];
    orow[lane + 32] = acc1 * inv - REF[i*DIM + lane + 32];
    orow[lane + 64] = acc2 * inv - REF[i*DIM + lane + 64];
    orow[lane + 96] = acc3 * inv - REF[i*DIM + lane + 96];
}

extern "C" void kernel_launch(void* const* d_in, const int* in_sizes, int n_in,
                              void* d_out, int out_size) {
    const float* a = (const float*)d_in[0];
    const float* c = (const float*)d_in[1];
    const float *X, *REF;
    if (in_sizes[0] == NREF * DIM) { REF = a; X = c; }
    else                           { X = a;  REF = c; }
    float* out = (float*)d_out;

    int warps = B_*NPTS + NREF;
    aux_kernel<<<(warps*32 + 255) / 256, 256>>>(X, REF);

    dim3 cg(NPTS/64, NREF/64, B_);
    c_kernel<<<cg, 256>>>(X, REF);

    colmin_kernel<<<(B_*NPTS)/256, 256>>>();
    sort_kernel<<<B_, 256>>>();
    permute_kernel<<<(B_*NREF)/4, 128>>>();

    sinkhorn_cluster<<<2 * B_, 1024>>>();

    bary_kernel<<<dim3(NREF/8, B_), 256>>>(X, REF, out);
}

// round 9
// speedup vs baseline: 1.6783x; 1.6783x over previous
#include <cuda_runtime.h>
#include <cstdint>
#include <math.h>

#define B_    64
#define NREF  256
#define NPTS  2048
#define DIM   128
#define LOG2E 1.44269504088896f
#define LW2X  (-5.5451748845f * LOG2E)   /* log(1/256 + 1e-8)  in log2 units */
#define LW2Y  (-7.6245985065f * LOG2E)   /* log(1/2048 + 1e-8) in log2 units */
#define ITERS 100
#define FULLM 0xffffffffu
#define NEG_INF __int_as_float(0xff800000)
#define TOLS2 0.0288539f                 /* 0.02 * log2e */

#define QSCALE 256000.0f                 /* 1000 * 256  */
#define QMAXF  8388607.0f                /* 2^23 - 1    */
#define MAGIC  0x4B000000u               /* 2^23 float  */
/* log2-domain step & bias: z2 = v2 - STEP2*q ; bias residual cancels between phases */
#define STEP2  (0.00390625f * LOG2E)
#define BIAS2  (STEP2 * 8388608.0f)
#define MARG2  21.64f                    /* 15 nats in log2 units */

// -------- device scratch (allocation-free per harness rules) --------
__device__ __align__(16) unsigned short g_Clo[(size_t)B_ * NREF * NPTS]; // low 16 bits of q
__device__ __align__(16) unsigned char  g_Chi[(size_t)B_ * NREF * NPTS]; // high 8 bits of q
__device__ float g_us[B_ * NREF];        // log2-domain scaled potentials
__device__ float g_vs[B_ * NPTS];
__device__ float g_x2[B_ * NPTS];
__device__ float g_r2[NREF];

__device__ __forceinline__ unsigned int smem_u32(const void* p) {
    unsigned int a;
    asm("{ .reg .u64 t; cvta.to.shared.u64 t, %1; cvt.u32.u64 %0, t; }" : "=r"(a) : "l"(p));
    return a;
}
__device__ __forceinline__ void st_peer_f32(unsigned int local_addr, int peer, float v) {
    unsigned int rem;
    asm volatile("mapa.shared::cluster.u32 %0, %1, %2;" : "=r"(rem) : "r"(local_addr), "r"(peer));
    asm volatile("st.shared::cluster.f32 [%0], %1;" :: "r"(rem), "f"(v) : "memory");
}
__device__ __forceinline__ void cluster_sync_() {
    asm volatile("barrier.cluster.arrive.aligned;" ::: "memory");
    asm volatile("barrier.cluster.wait.aligned;" ::: "memory");
}

// -------- squared norms --------
__global__ void aux_kernel(const float* __restrict__ X, const float* __restrict__ REF) {
    int gw   = (blockIdx.x * blockDim.x + threadIdx.x) >> 5;
    int lane = threadIdx.x & 31;
    if (gw < B_ * NPTS) {
        const float* r = X + (size_t)gw * DIM;
        float s = 0.f;
        #pragma unroll
        for (int k = lane; k < DIM; k += 32) { float t = r[k]; s = fmaf(t, t, s); }
        #pragma unroll
        for (int o = 16; o; o >>= 1) s += __shfl_xor_sync(FULLM, s, o);
        if (!lane) g_x2[gw] = s;
    } else if (gw < B_ * NPTS + NREF) {
        int i = gw - B_ * NPTS;
        const float* r = REF + i * DIM;
        float s = 0.f;
        #pragma unroll
        for (int k = lane; k < DIM; k += 32) { float t = r[k]; s = fmaf(t, t, s); }
        #pragma unroll
        for (int o = 16; o; o >>= 1) s += __shfl_xor_sync(FULLM, s, o);
        if (!lane) g_r2[i] = s;
    }
}

// -------- build 24-bit quantized cost: q = round(256000 * dist) --------
__global__ __launch_bounds__(256) void c_kernel(const float* __restrict__ X,
                                                const float* __restrict__ REF) {
    __shared__ float sA[32][65];
    __shared__ float sB[32][65];
    int b  = blockIdx.z;
    int i0 = blockIdx.y * 64, j0 = blockIdx.x * 64;
    int tid = threadIdx.x;
    int ti = tid >> 4, tj = tid & 15;
    const float* Xb = X + (size_t)b * NPTS * DIM;

    float acc[4][4];
    #pragma unroll
    for (int a = 0; a < 4; a++)
        #pragma unroll
        for (int c = 0; c < 4; c++) acc[a][c] = 0.f;

    for (int k0 = 0; k0 < DIM; k0 += 32) {
        #pragma unroll
        for (int r = 0; r < 8; r++) {
            int e  = r * 256 + tid;
            int ii = e >> 5, kk = e & 31;
            sA[kk][ii] = REF[(i0 + ii) * DIM + k0 + kk];
            sB[kk][ii] = Xb[(size_t)(j0 + ii) * DIM + k0 + kk];
        }
        __syncthreads();
        #pragma unroll
        for (int kk = 0; kk < 32; kk++) {
            float a0 = sA[kk][ti*4+0], a1 = sA[kk][ti*4+1], a2 = sA[kk][ti*4+2], a3 = sA[kk][ti*4+3];
            float b0 = sB[kk][tj*4+0], b1 = sB[kk][tj*4+1], b2 = sB[kk][tj*4+2], b3 = sB[kk][tj*4+3];
            acc[0][0]=fmaf(a0,b0,acc[0][0]); acc[0][1]=fmaf(a0,b1,acc[0][1]); acc[0][2]=fmaf(a0,b2,acc[0][2]); acc[0][3]=fmaf(a0,b3,acc[0][3]);
            acc[1][0]=fmaf(a1,b0,acc[1][0]); acc[1][1]=fmaf(a1,b1,acc[1][1]); acc[1][2]=fmaf(a1,b2,acc[1][2]); acc[1][3]=fmaf(a1,b3,acc[1][3]);
            acc[2][0]=fmaf(a2,b0,acc[2][0]); acc[2][1]=fmaf(a2,b1,acc[2][1]); acc[2][2]=fmaf(a2,b2,acc[2][2]); acc[2][3]=fmaf(a2,b3,acc[2][3]);
            acc[3][0]=fmaf(a3,b0,acc[3][0]); acc[3][1]=fmaf(a3,b1,acc[3][1]); acc[3][2]=fmaf(a3,b2,acc[3][2]); acc[3][3]=fmaf(a3,b3,acc[3][3]);
        }
        __syncthreads();
    }

    float x20 = g_x2[b*NPTS + j0 + tj*4 + 0];
    float x21 = g_x2[b*NPTS + j0 + tj*4 + 1];
    float x22 = g_x2[b*NPTS + j0 + tj*4 + 2];
    float x23 = g_x2[b*NPTS + j0 + tj*4 + 3];
    #pragma unroll
    for (int a = 0; a < 4; a++) {
        int i = i0 + ti*4 + a;
        float r2 = g_r2[i];
        float d0 = sqrtf(fmaxf(r2 + x20 - 2.f*acc[a][0], 0.f));
        float d1 = sqrtf(fmaxf(r2 + x21 - 2.f*acc[a][1], 0.f));
        float d2 = sqrtf(fmaxf(r2 + x22 - 2.f*acc[a][2], 0.f));
        float d3 = sqrtf(fmaxf(r2 + x23 - 2.f*acc[a][3], 0.f));
        unsigned q0 = __float2uint_rn(fminf(QSCALE*d0, QMAXF));
        unsigned q1 = __float2uint_rn(fminf(QSCALE*d1, QMAXF));
        unsigned q2 = __float2uint_rn(fminf(QSCALE*d2, QMAXF));
        unsigned q3 = __float2uint_rn(fminf(QSCALE*d3, QMAXF));
        size_t idx = ((size_t)b*NREF + i)*NPTS + j0 + tj*4;
        ushort4 lo;
        lo.x = (unsigned short)(q0 & 0xFFFF);
        lo.y = (unsigned short)(q1 & 0xFFFF);
        lo.z = (unsigned short)(q2 & 0xFFFF);
        lo.w = (unsigned short)(q3 & 0xFFFF);
        *(ushort4*)(&g_Clo[idx]) = lo;
        uchar4 hi;
        hi.x = (unsigned char)(q0 >> 16);
        hi.y = (unsigned char)(q1 >> 16);
        hi.z = (unsigned char)(q2 >> 16);
        hi.w = (unsigned char)(q3 >> 16);
        *(uchar4*)(&g_Chi[idx]) = hi;
    }
}

// -------- cluster Sinkhorn, log2 domain, batched loads --------
__global__ __launch_bounds__(1024, 1) __cluster_dims__(2, 1, 1)
void sinkhorn_cluster() {
    __shared__ __align__(16) float us [NREF];   // log2-domain u
    __shared__ __align__(16) float usb[NREF];   // us + BIAS2
    __shared__ __align__(16) float vs [NPTS];
    __shared__ __align__(16) float vsb[NPTS];
    __shared__ __align__(16) float pmP[NPTS];   // peer partial max
    __shared__ __align__(16) float psP[NPTS];   // peer partial sum
    __shared__ float red[32];
    __shared__ float s_dmu, s_dmuP;
    __shared__ int   s_done;

    int b    = blockIdx.x >> 1;
    int rank = blockIdx.x & 1;
    int peer = rank ^ 1;
    int tid = threadIdx.x, lane = tid & 31, w = tid >> 5;
    const unsigned short* CbLo = g_Clo + (size_t)b * NREF * NPTS;
    const unsigned char*  CbHi = g_Chi + (size_t)b * NREF * NPTS;

    unsigned int pm_a  = smem_u32(pmP);
    unsigned int ps_a  = smem_u32(psP);
    unsigned int dmu_a = smem_u32(&s_dmuP);

    if (tid < NREF) { us[tid] = 0.f; usb[tid] = BIAS2; }
    vs[tid] = 0.f;  vs[tid + 1024] = 0.f;
    vsb[tid] = BIAS2; vsb[tid + 1024] = BIAS2;
    __syncthreads();

    for (int iter = 0; iter < ITERS; iter++) {
        // ======== u phase: warp w -> rows rank*128 + w*4 .. +3 ========
        float udmax = 0.f;
        #pragma unroll 1
        for (int r = 0; r < 4; r++) {
            int i = rank * 128 + w * 4 + r;
            const uint4* rlo = (const uint4*)(CbLo + (size_t)i * NPTS);
            const uint2* rhi = (const uint2*)(CbHi + (size_t)i * NPTS);
            float m = NEG_INF, s = 0.f;
            #pragma unroll 1
            for (int half = 0; half < 2; half++) {
                uint4 lo[4]; uint2 hv[4];
                #pragma unroll
                for (int t = 0; t < 4; t++) {        // batched: MLP 8
                    int k = lane + 32*(half*4 + t);
                    lo[t] = rlo[k];
                    hv[t] = rhi[k];
                }
                #pragma unroll
                for (int t = 0; t < 4; t++) {
                    int j0 = (lane + 32*(half*4 + t)) * 8;
                    float4 va = *(const float4*)&vsb[j0];
                    float4 vb = *(const float4*)&vsb[j0 + 4];
                    float f0 = __uint_as_float(MAGIC | ((hv[t].x << 16) & 0xFF0000u) | (lo[t].x & 0xFFFFu));
                    float f1 = __uint_as_float(MAGIC | ((hv[t].x <<  8) & 0xFF0000u) | (lo[t].x >> 16));
                    float f2 = __uint_as_float(MAGIC | ( hv[t].x        & 0xFF0000u) | (lo[t].y & 0xFFFFu));
                    float f3 = __uint_as_float(MAGIC | ((hv[t].x >>  8) & 0xFF0000u) | (lo[t].y >> 16));
                    float f4 = __uint_as_float(MAGIC | ((hv[t].y << 16) & 0xFF0000u) | (lo[t].z & 0xFFFFu));
                    float f5 = __uint_as_float(MAGIC | ((hv[t].y <<  8) & 0xFF0000u) | (lo[t].z >> 16));
                    float f6 = __uint_as_float(MAGIC | ( hv[t].y        & 0xFF0000u) | (lo[t].w & 0xFFFFu));
                    float f7 = __uint_as_float(MAGIC | ((hv[t].y >>  8) & 0xFF0000u) | (lo[t].w >> 16));
                    float z0 = fmaf(-STEP2, f0, va.x);
                    float z1 = fmaf(-STEP2, f1, va.y);
                    float z2 = fmaf(-STEP2, f2, va.z);
                    float z3 = fmaf(-STEP2, f3, va.w);
                    float z4 = fmaf(-STEP2, f4, vb.x);
                    float z5 = fmaf(-STEP2, f5, vb.y);
                    float z6 = fmaf(-STEP2, f6, vb.z);
                    float z7 = fmaf(-STEP2, f7, vb.w);
                    float lm = fmaxf(fmaxf(fmaxf(z0, z1), fmaxf(z2, z3)),
                                     fmaxf(fmaxf(z4, z5), fmaxf(z6, z7)));
                    if (lm > m - MARG2) {
                        float nm = fmaxf(m, lm);
                        s *= exp2f(m - nm);
                        if (z0 > nm - MARG2) s += exp2f(z0 - nm);
                        if (z1 > nm - MARG2) s += exp2f(z1 - nm);
                        if (z2 > nm - MARG2) s += exp2f(z2 - nm);
                        if (z3 > nm - MARG2) s += exp2f(z3 - nm);
                        if (z4 > nm - MARG2) s += exp2f(z4 - nm);
                        if (z5 > nm - MARG2) s += exp2f(z5 - nm);
                        if (z6 > nm - MARG2) s += exp2f(z6 - nm);
                        if (z7 > nm - MARG2) s += exp2f(z7 - nm);
                        m = nm;
                    }
                }
            }
            #pragma unroll
            for (int o = 16; o; o >>= 1) {
                float mo = __shfl_xor_sync(FULLM, m, o);
                float so = __shfl_xor_sync(FULLM, s, o);
                float nm = fmaxf(m, mo);
                s = s * exp2f(m - nm) + so * exp2f(mo - nm);
                m = nm;
            }
            float nu = LW2X - (m + __log2f(s));
            if (lane == 0) {
                udmax = fmaxf(udmax, fabsf(nu - us[i]));
                us[i]  = nu;
                usb[i] = nu + BIAS2;
            }
        }
        if (lane == 0) red[w] = udmax;
        __syncthreads();          // us/usb own half ready
        if (tid == 0) {
            float dm = 0.f;
            #pragma unroll
            for (int q = 0; q < 32; q++) dm = fmaxf(dm, red[q]);
            s_dmu = dm;
        }

        // ======== v partials over OWN rows: thread -> cols 2*tid, 2*tid+1 ========
        int j0 = 2 * tid;
        float m0 = NEG_INF, s0 = 0.f;
        float m1 = NEG_INF, s1 = 0.f;
        int ibase = rank * 128;
        #pragma unroll 1
        for (int ii = 0; ii < 128; ii += 8) {
            unsigned lo32[8]; unsigned short hi16[8];
            #pragma unroll
            for (int k = 0; k < 8; k++) {            // batched: MLP 16
                int i = ibase + ii + k;
                lo32[k] = ((const unsigned*)(CbLo + (size_t)i * NPTS))[tid];
                hi16[k] = ((const unsigned short*)(CbHi + (size_t)i * NPTS))[tid];
            }
            #pragma unroll
            for (int k = 0; k < 8; k++) {
                int i = ibase + ii + k;
                float ub = usb[i];
                float f0 = __uint_as_float(MAGIC | (((unsigned)hi16[k] << 16) & 0xFF0000u) | (lo32[k] & 0xFFFFu));
                float f1 = __uint_as_float(MAGIC | (((unsigned)hi16[k] <<  8) & 0xFF0000u) | (lo32[k] >> 16));
                float z0 = fmaf(-STEP2, f0, ub);
                float z1 = fmaf(-STEP2, f1, ub);
                if (z0 > m0 - MARG2) {
                    float nm = fmaxf(m0, z0);
                    s0 = s0 * exp2f(m0 - nm) + exp2f(z0 - nm);
                    m0 = nm;
                }
                if (z1 > m1 - MARG2) {
                    float nm = fmaxf(m1, z1);
                    s1 = s1 * exp2f(m1 - nm) + exp2f(z1 - nm);
                    m1 = nm;
                }
            }
        }
        // push partials + own u-dmax to peer
        st_peer_f32(pm_a + 4u*j0,     peer, m0);
        st_peer_f32(ps_a + 4u*j0,     peer, s0);
        st_peer_f32(pm_a + 4u*(j0+1), peer, m1);
        st_peer_f32(ps_a + 4u*(j0+1), peer, s1);
        if (tid == 0) st_peer_f32(dmu_a, peer, s_dmu);

        cluster_sync_();          // (1) publish partials both ways

        // ======== merge partials -> full v (identical on both CTAs) ========
        float vdm;
        {
            float pm = pmP[j0], ps = psP[j0];
            float M  = fmaxf(m0, pm);
            float S  = s0 * exp2f(m0 - M) + ps * exp2f(pm - M);
            float nv0 = LW2Y - (M + __log2f(S));
            float pm2 = pmP[j0+1], ps2 = psP[j0+1];
            float M2  = fmaxf(m1, pm2);
            float S2  = s1 * exp2f(m1 - M2) + ps2 * exp2f(pm2 - M2);
            float nv1 = LW2Y - (M2 + __log2f(S2));
            vdm = fmaxf(fabsf(nv0 - vs[j0]), fabsf(nv1 - vs[j0+1]));
            vs[j0]   = nv0;  vsb[j0]   = nv0 + BIAS2;
            vs[j0+1] = nv1;  vsb[j0+1] = nv1 + BIAS2;
        }

        // ======== convergence ========
        #pragma unroll
        for (int o = 16; o; o >>= 1) vdm = fmaxf(vdm, __shfl_xor_sync(FULLM, vdm, o));
        if (lane == 0) red[w] = vdm;
        __syncthreads();
        if (tid == 0) {
            float dm = 0.f;
            #pragma unroll
            for (int q = 0; q < 32; q++) dm = fmaxf(dm, red[q]);
            dm = fmaxf(dm, fmaxf(s_dmu, s_dmuP));
            s_done = (dm < TOLS2) ? 1 : 0;
        }
        cluster_sync_();          // (2) merges done -> partial buffers reusable
        if (s_done) break;
    }

    // export: each rank its own u half; rank 0 exports full v
    if (tid < 128) g_us[b*NREF + rank*128 + tid] = us[rank*128 + tid];
    if (rank == 0) {
        g_vs[b*NPTS + tid]        = vs[tid];
        g_vs[b*NPTS + tid + 1024] = vs[tid + 1024];
    }
    cluster_sync_();
}

// -------- barycenters: log2-domain weights + ballot X gather --------
__global__ __launch_bounds__(256) void bary_kernel(const float* __restrict__ X,
                                                   const float* __restrict__ REF,
                                                   float* __restrict__ out) {
    __shared__ float vsb[NPTS];
    int b = blockIdx.y, tid = threadIdx.x, lane = tid & 31, w = tid >> 5;
    const float* vrow = g_vs + b * NPTS;
    #pragma unroll
    for (int r = 0; r < NPTS/256; r++) vsb[r*256 + tid] = vrow[r*256 + tid] + BIAS2;
    __syncthreads();

    int i = blockIdx.x * 8 + w;
    float ui = g_us[b*NREF + i];
    const unsigned short* Clor = g_Clo + ((size_t)b*NREF + i) * NPTS;
    const unsigned char*  Chir = g_Chi + ((size_t)b*NREF + i) * NPTS;
    const float* Xb = X + (size_t)b * NPTS * DIM;

    float acc0 = 0.f, acc1 = 0.f, acc2 = 0.f, acc3 = 0.f, den = 0.f;
    for (int jb = 0; jb < NPTS; jb += 32) {
        int j = jb + lane;
        unsigned lo = Clor[j];
        unsigned hi = Chir[j];
        float f = __uint_as_float(MAGIC | (hi << 16) | lo);
        float z = fmaf(-STEP2, f, ui + vsb[j]);
        float wgt = 0.f;
        bool flag = z > -57.7f;                    /* e^-40 in log2 units */
        if (flag) wgt = exp2f(z);
        unsigned act = __ballot_sync(FULLM, flag);
        while (act) {
            int p = __ffs(act) - 1; act &= act - 1;
            float wj = __shfl_sync(FULLM, wgt, p);
            const float* xr = Xb + (size_t)(jb + p) * DIM;
            acc0 = fmaf(wj, xr[lane     ], acc0);
            acc1 = fmaf(wj, xr[lane + 32], acc1);
            acc2 = fmaf(wj, xr[lane + 64], acc2);
            acc3 = fmaf(wj, xr[lane + 96], acc3);
            den += wj;
        }
    }
    float inv = 1.f / (den + 1e-8f);
    float* orow = out + ((size_t)b*NREF + i) * DIM;
    orow[lane     ] = acc0 * inv - REF[i*DIM + lane     ];
    orow[lane + 32] = acc1 * inv - REF[i*DIM + lane + 32];
    orow[lane + 64] = acc2 * inv - REF[i*DIM + lane + 64];
    orow[lane + 96] = acc3 * inv - REF[i*DIM + lane + 96];
}

extern "C" void kernel_launch(void* const* d_in, const int* in_sizes, int n_in,
                              void* d_out, int out_size) {
    const float* a = (const float*)d_in[0];
    const float* c = (const float*)d_in[1];
    const float *X, *REF;
    if (in_sizes[0] == NREF * DIM) { REF = a; X = c; }
    else                           { X = a;  REF = c; }
    float* out = (float*)d_out;

    int warps = B_*NPTS + NREF;
    aux_kernel<<<(warps*32 + 255) / 256, 256>>>(X, REF);

    dim3 cg(NPTS/64, NREF/64, B_);
    c_kernel<<<cg, 256>>>(X, REF);

    sinkhorn_cluster<<<2 * B_, 1024>>>();

    bary_kernel<<<dim3(NREF/8, B_), 256>>>(X, REF, out);
}